// round 10
// baseline (speedup 1.0000x reference)
#include <cuda_runtime.h>
#include <cuda_fp16.h>
#include <cstdint>

#define BATCH 1024
#define TT 13
#define YY 188
#define HH 512
#define GG 1536
#define DS 13
#define KPAD 192
#define NTH 128
#define SEPIL 100

// ---------------- scratch ----------------
__device__ float  g_xg0[(size_t)TT * BATCH * GG];   // ring: xg0 + b_ih0 (permuted cols)
__device__ float  g_gh1[(size_t)BATCH * GG];
__device__ float  g_h0[2][(size_t)BATCH * HH];
__device__ __half g_h0f[2][(size_t)BATCH * HH];
__device__ float  g_h1[2][(size_t)BATCH * HH];
__device__ __half g_h1f[2][(size_t)BATCH * HH];
__device__ float  g_xlast[(size_t)BATCH * YY];
__device__ __half g_xlastf[(size_t)BATCH * KPAD];
__device__ __half g_xpf[(size_t)BATCH * TT * KPAD];
__device__ __half g_Whh0h[(size_t)GG * HH];
__device__ __half g_Wih1h[(size_t)GG * HH];
__device__ __half g_Whh1h[(size_t)GG * HH];
__device__ __half g_Wih0h[(size_t)GG * KPAD];
__device__ __half g_Wouth[(size_t)KPAD * HH];
__device__ float g_bih0p[GG], g_bhh0p[GG], g_bih1p[GG], g_bhh1p[GG];

// ---------------- helpers ----------------
__device__ __forceinline__ void cp16(uint32_t d, const void* s) {
    asm volatile("cp.async.cg.shared.global [%0], [%1], 16;\n" :: "r"(d), "l"(s));
}
__device__ __forceinline__ void cpc()  { asm volatile("cp.async.commit_group;\n"); }
__device__ __forceinline__ void cpw1() { asm volatile("cp.async.wait_group 1;\n"); }
__device__ __forceinline__ void gdwait() {
    asm volatile("griddepcontrol.wait;" ::: "memory");
}
__device__ __forceinline__ void gdlaunch() {
    asm volatile("griddepcontrol.launch_dependents;" ::: "memory");
}
__device__ __forceinline__ float sigm(float x)   { return 1.f / (1.f + __expf(-x)); }
__device__ __forceinline__ float tanhf_(float x) { return 2.f * sigm(2.f * x) - 1.f; }

__device__ __forceinline__ void ldm4(uint32_t* r, uint32_t a) {
    asm volatile("ldmatrix.sync.aligned.m8n8.x4.shared.b16 {%0,%1,%2,%3}, [%4];"
        : "=r"(r[0]), "=r"(r[1]), "=r"(r[2]), "=r"(r[3]) : "r"(a));
}
__device__ __forceinline__ uint32_t relu2(uint32_t v) {
    uint32_t r; asm("max.f16x2 %0, %1, %2;" : "=r"(r) : "r"(v), "r"(0u)); return r;
}
__device__ __forceinline__ void mma16(float* d, const uint32_t* a, uint32_t b0, uint32_t b1) {
    asm volatile("mma.sync.aligned.m16n8k16.row.col.f32.f16.f16.f32 "
        "{%0,%1,%2,%3},{%4,%5,%6,%7},{%8,%9},{%0,%1,%2,%3};"
        : "+f"(d[0]), "+f"(d[1]), "+f"(d[2]), "+f"(d[3])
        : "r"(a[0]), "r"(a[1]), "r"(a[2]), "r"(a[3]), "r"(b0), "r"(b1));
}

// modes
#define M_GATE0 0
#define M_GATE1 1
#define M_STORE 2
#define M_XGALL 4
#define M_OUT   5

// ---- GEMM core: BM=64, BN=96, 4 warps (2x2), BK=64 halves, 2-stage, occ 4 ----
#define ASTR  8192      // 64*128 bytes per A stage
#define BSTRb 12288     // 96*128 bytes per B stage
#define SMEMB (2 * (ASTR + BSTRb))   // 40960

template<int MODE, int NK, bool ZG, bool RELU_A>
__device__ __forceinline__ void gcore(
    int m0, int n0,
    const __half* __restrict__ A, int lda,
    const __half* __restrict__ Bw, int ldb,
    const float* __restrict__ biasg,
    const float* __restrict__ gh, const float* __restrict__ bhh,
    const float* __restrict__ hsrc, float* __restrict__ hdst, __half* __restrict__ hdstf,
    float* __restrict__ C, float* __restrict__ dout, int dstep)
{
    extern __shared__ float sm[];
    const uint32_t sAb = (uint32_t)__cvta_generic_to_shared(sm);
    const uint32_t sBb = sAb + 2 * ASTR;

    const int tid = threadIdx.x, lane = tid & 31, warp = tid >> 5;
    const int warpM = warp >> 1, warpN = warp & 1;     // 2 x 2
    const int lane4 = lane >> 2, lq = lane & 3;

    float acc[2][6][4];
#pragma unroll
    for (int i = 0; i < 2; i++)
#pragma unroll
        for (int j = 0; j < 6; j++)
#pragma unroll
            for (int q = 0; q < 4; q++) acc[i][j][q] = 0.f;

    auto loadA = [&](int st, int k0) {
#pragma unroll
        for (int v = tid; v < 64 * 8; v += NTH) {
            int r = v >> 3, vc = v & 7;
            cp16(sAb + st * ASTR + r * 128 + ((vc ^ (r & 7)) << 4),
                 A + (size_t)(m0 + r) * lda + k0 + vc * 8);
        }
    };
    auto loadB = [&](int st, int k0) {
#pragma unroll
        for (int v = tid; v < 96 * 8; v += NTH) {
            int r = v >> 3, vc = v & 7;
            cp16(sBb + st * BSTRb + r * 128 + ((vc ^ (r & 7)) << 4),
                 Bw + (size_t)(n0 + r) * ldb + k0 + vc * 8);
        }
    };

    // B (weights) for both stages has NO dependency on the predecessor kernel:
    // issue before griddepcontrol.wait so it overlaps the predecessor's tail.
    loadB(0, 0);
    loadB(1, 64);
    gdwait();                        // predecessor results now visible
    loadA(0, 0);  cpc();             // G0 = {B0,B1,A0}
    loadA(1, 64); cpc();             // G1 = {A1}

    const int subrow = lane & 7;
    uint32_t aBase[2]; int r7A[2];
#pragma unroll
    for (int i = 0; i < 2; i++) {
        int row = warpM * 32 + i * 16 + subrow + ((lane >> 3) & 1) * 8;
        aBase[i] = sAb + row * 128; r7A[i] = row & 7;
    }
    uint32_t bBase[3]; int r7B[3];
#pragma unroll
    for (int jj = 0; jj < 3; jj++) {
        int row = warpN * 48 + jj * 16 + subrow + (lane >> 4) * 8;
        bBase[jj] = sBb + row * 128; r7B[jj] = row & 7;
    }
    const int kvA = lane >> 4;
    const int kvB = (lane >> 3) & 1;

    for (int kt = 0; kt < NK; kt++) {
        cpw1();                       // all groups except newest done -> stage kt ready
        __syncthreads();
        const int st = kt & 1;
#pragma unroll
        for (int ks = 0; ks < 4; ks++) {
            uint32_t aF[2][4], bF[3][4];
#pragma unroll
            for (int i = 0; i < 2; i++) {
                ldm4(aF[i], aBase[i] + st * ASTR + (((2 * ks + kvA) ^ r7A[i]) << 4));
                if (RELU_A) {
#pragma unroll
                    for (int q = 0; q < 4; q++) aF[i][q] = relu2(aF[i][q]);
                }
            }
#pragma unroll
            for (int jj = 0; jj < 3; jj++)
                ldm4(bF[jj], bBase[jj] + st * BSTRb + (((2 * ks + kvB) ^ r7B[jj]) << 4));
#pragma unroll
            for (int j = 0; j < 6; j++)
#pragma unroll
                for (int i = 0; i < 2; i++)
                    mma16(acc[i][j], aF[i],
                          bF[j >> 1][(j & 1) * 2], bF[j >> 1][(j & 1) * 2 + 1]);
        }
        __syncthreads();              // stage st fully consumed by ALL warps
        if (kt + 2 < NK) {            // refill the just-freed buffer with stage kt+2
            loadB(st, (kt + 2) * 64);
            loadA(st, (kt + 2) * 64);
        }
        cpc();                        // unconditional: keeps group<->stage invariant
    }

    // ---------------- epilogues ----------------
    if (MODE == M_STORE || MODE == M_XGALL) {
#pragma unroll
        for (int i = 0; i < 2; i++) {
            int rr = m0 + warpM * 32 + i * 16 + lane4;
#pragma unroll
            for (int j = 0; j < 6; j++) {
                int cc = n0 + warpN * 48 + j * 8 + lq * 2;
#pragma unroll
                for (int q = 0; q < 4; q++) {
                    int r2 = rr + (q >> 1) * 8, c2 = cc + (q & 1);
                    float v = acc[i][j][q] + biasg[c2];
                    if (MODE == M_STORE) {
                        C[(size_t)r2 * GG + c2] = v;
                    } else {
                        int b = r2 / TT, t = r2 % TT;
                        C[((size_t)t * BATCH + b) * GG + c2] = v;
                    }
                }
            }
        }
    } else if (MODE == M_OUT) {
#pragma unroll
        for (int i = 0; i < 2; i++) {
            int rr = m0 + warpM * 32 + i * 16 + lane4;
#pragma unroll
            for (int j = 0; j < 6; j++) {
                int cc = n0 + warpN * 48 + j * 8 + lq * 2;
#pragma unroll
                for (int q = 0; q < 4; q++) {
                    int r2 = rr + (q >> 1) * 8, c2 = cc + (q & 1);
                    if (c2 < YY) {
                        float v = acc[i][j][q] + biasg[c2] + g_xlast[(size_t)r2 * YY + c2];
                        dout[((size_t)r2 * DS + dstep) * YY + c2] = v;
                        g_xlast[(size_t)r2 * YY + c2] = v;
                        g_xlastf[(size_t)r2 * KPAD + c2] = __float2half_rn(v);
                    }
                }
            }
        }
    } else {  // M_GATE0 / M_GATE1: acc -> smem -> fused gate math
#pragma unroll
        for (int i = 0; i < 2; i++) {
            int rl = warpM * 32 + i * 16 + lane4;
#pragma unroll
            for (int j = 0; j < 6; j++) {
                int cl = warpN * 48 + j * 8 + lq * 2;
                *(float2*)&sm[rl * SEPIL + cl]       = make_float2(acc[i][j][0], acc[i][j][1]);
                *(float2*)&sm[(rl + 8) * SEPIL + cl] = make_float2(acc[i][j][2], acc[i][j][3]);
            }
        }
        __syncthreads();
        const int jbase = n0 / 3;   // 32 * blockIdx.x
        for (int idx = tid; idx < 64 * 32; idx += NTH) {
            int bl = idx >> 5, jj = idx & 31;
            int b = m0 + bl;
            int cg = n0 + 3 * jj;
            float ar = sm[bl * SEPIL + 3 * jj + 0];
            float az = sm[bl * SEPIL + 3 * jj + 1];
            float an = sm[bl * SEPIL + 3 * jj + 2];
            float xr, xz, xn, gr, gz, gn, hp;
            if (MODE == M_GATE0) {
                const float* xg = gh + (size_t)b * GG;
                xr = xg[cg]; xz = xg[cg + 1]; xn = xg[cg + 2];
                gr = ar + bhh[cg]; gz = az + bhh[cg + 1]; gn = an + bhh[cg + 2];
                hp = hsrc[(size_t)b * HH + jbase + jj];
            } else {
                xr = ar + biasg[cg]; xz = az + biasg[cg + 1]; xn = an + biasg[cg + 2];
                if (ZG) {
                    gr = bhh[cg]; gz = bhh[cg + 1]; gn = bhh[cg + 2]; hp = 0.f;
                } else {
                    const float* g = gh + (size_t)b * GG;
                    gr = g[cg]; gz = g[cg + 1]; gn = g[cg + 2];
                    hp = hsrc[(size_t)b * HH + jbase + jj];
                }
            }
            float r = sigm(xr + gr), z = sigm(xz + gz);
            float nn_ = tanhf_(xn + r * gn);
            float hv = (1.f - z) * nn_ + z * hp;
            hdst[(size_t)b * HH + jbase + jj] = hv;
            hdstf[(size_t)b * HH + jbase + jj] = __float2half_rn(hv);
        }
    }
}

// ---------------- kernels ----------------
__global__ void __launch_bounds__(NTH, 4) k_rec(int par, int slot) {
    int m0 = blockIdx.y * 64, n0 = blockIdx.x * 96;
    if (blockIdx.z == 0)
        gcore<M_GATE0, 8, false, false>(m0, n0,
            g_h0f[par ^ 1], HH, g_Whh0h, HH, nullptr,
            g_xg0 + (size_t)slot * BATCH * GG, g_bhh0p,
            g_h0[par ^ 1], g_h0[par], g_h0f[par], nullptr, nullptr, 0);
    else
        gcore<M_STORE, 8, false, false>(m0, n0,
            g_h1f[par ^ 1], HH, g_Whh1h, HH, g_bhh1p,
            nullptr, nullptr, nullptr, nullptr, nullptr, g_gh1, nullptr, 0);
    gdlaunch();
}

template<bool ZG>
__global__ void __launch_bounds__(NTH, 4) k_xg1(int par) {
    gcore<M_GATE1, 8, ZG, false>(blockIdx.y * 64, blockIdx.x * 96,
        g_h0f[par], HH, g_Wih1h, HH, g_bih1p, g_gh1, g_bhh1p,
        g_h1[par ^ 1], g_h1[par], g_h1f[par], nullptr, nullptr, 0);
    gdlaunch();
}

__global__ void __launch_bounds__(NTH, 4) k_xg0_all() {
    gcore<M_XGALL, 3, false, false>(blockIdx.y * 64, blockIdx.x * 96,
        g_xpf, KPAD, g_Wih0h, KPAD, g_bih0p,
        nullptr, nullptr, nullptr, nullptr, nullptr, g_xg0, nullptr, 0);
}

__global__ void __launch_bounds__(NTH, 4) k_xg0_new(int slot) {
    gcore<M_STORE, 3, false, false>(blockIdx.y * 64, blockIdx.x * 96,
        g_xlastf, KPAD, g_Wih0h, KPAD, g_bih0p,
        nullptr, nullptr, nullptr, nullptr, nullptr,
        g_xg0 + (size_t)slot * BATCH * GG, nullptr, 0);
    gdlaunch();
}

// grid (16,16,2):
//   z=0, x<2 : output GEMM (+residual+feedback)   [32 CTAs]
//   z=1      : gate0 init for NEXT decode's ring slot [256 CTAs]
__global__ void __launch_bounds__(NTH, 4) k_out(float* __restrict__ dout, int dstep,
                                                const float* __restrict__ bout,
                                                int nextslot) {
    if (blockIdx.z == 1) {
        if (nextslot >= 0) {
            gdwait();
            const float* ring = g_xg0 + (size_t)nextslot * BATCH * GG;
            int base = (blockIdx.y * gridDim.x + blockIdx.x) * NTH + threadIdx.x;
            int stride = gridDim.x * gridDim.y * NTH;
            for (int idx = base; idx < BATCH * HH; idx += stride) {
                int b = idx >> 9, j = idx & 511;
                const float* xg = ring + (size_t)b * GG;
                int c = 3 * j;
                float r = sigm(xg[c] + g_bhh0p[c]);
                float z = sigm(xg[c + 1] + g_bhh0p[c + 1]);
                float n = tanhf_(xg[c + 2] + r * g_bhh0p[c + 2]);
                float hv = (1.f - z) * n;
                g_h0[0][idx] = hv;
                g_h0f[0][idx] = __float2half_rn(hv);
            }
        }
        gdlaunch();
        return;
    }
    if (blockIdx.x < 2) {
        gcore<M_OUT, 8, false, true>(blockIdx.y * 64, blockIdx.x * 96,
            g_h1f[0], HH, g_Wouth, HH, bout, nullptr, nullptr,
            nullptr, nullptr, nullptr, nullptr, dout, dstep);
    }
    gdlaunch();
}

__global__ void k_gate0_init(int slot) {
    int idx = blockIdx.x * blockDim.x + threadIdx.x;
    if (idx >= BATCH * HH) return;
    int b = idx >> 9, j = idx & 511;
    const float* xg = g_xg0 + (size_t)slot * BATCH * GG + (size_t)b * GG;
    int c = 3 * j;
    float r = sigm(xg[c] + g_bhh0p[c]);
    float z = sigm(xg[c + 1] + g_bhh0p[c + 1]);
    float n = tanhf_(xg[c + 2] + r * g_bhh0p[c + 2]);
    float hv = (1.f - z) * n;
    g_h0[0][idx] = hv;
    g_h0f[0][idx] = __float2half_rn(hv);
}

__global__ void k_init(const float* __restrict__ x) {
    int idx = blockIdx.x * blockDim.x + threadIdx.x;
    if (idx < BATCH * TT * KPAD) {
        int row = idx / KPAD, k = idx % KPAD;
        g_xpf[idx] = (k < YY) ? __float2half_rn(x[(size_t)row * YY + k]) : __float2half_rn(0.f);
    }
    if (idx < BATCH * KPAD) {
        int b = idx / KPAD, k = idx % KPAD;
        if (k < YY) {
            float v = x[((size_t)b * TT + (TT - 1)) * YY + k];
            g_xlast[(size_t)b * YY + k] = v;
            g_xlastf[idx] = __float2half_rn(v);
        } else {
            g_xlastf[idx] = __float2half_rn(0.f);
        }
    }
}

__global__ void k_prep(const float* __restrict__ Wih0, const float* __restrict__ Whh0,
                       const float* __restrict__ bih0, const float* __restrict__ bhh0,
                       const float* __restrict__ Wih1, const float* __restrict__ Whh1,
                       const float* __restrict__ bih1, const float* __restrict__ bhh1,
                       const float* __restrict__ Wout) {
    int i = blockIdx.x * blockDim.x + threadIdx.x;
    if (i < GG * HH) {
        int c = i / HH, k = i % HH;
        int pr = (c % 3) * HH + c / 3;
        g_Whh0h[i] = __float2half_rn(Whh0[(size_t)pr * HH + k]);
        g_Wih1h[i] = __float2half_rn(Wih1[(size_t)pr * HH + k]);
        g_Whh1h[i] = __float2half_rn(Whh1[(size_t)pr * HH + k]);
    }
    if (i < GG * KPAD) {
        int c = i / KPAD, k = i % KPAD;
        int pr = (c % 3) * HH + c / 3;
        g_Wih0h[i] = (k < YY) ? __float2half_rn(Wih0[(size_t)pr * YY + k]) : __float2half_rn(0.f);
    }
    if (i < KPAD * HH) {
        int r = i / HH, k = i % HH;
        g_Wouth[i] = (r < YY) ? __float2half_rn(Wout[(size_t)r * HH + k]) : __float2half_rn(0.f);
    }
    if (i < GG) {
        int pr = (i % 3) * HH + i / 3;
        g_bih0p[i] = bih0[pr];
        g_bhh0p[i] = bhh0[pr];
        g_bih1p[i] = bih1[pr];
        g_bhh1p[i] = bhh1[pr];
    }
}

// ---------------- host ----------------
static void launch_pdl(const void* func, dim3 grid, dim3 block, size_t smem, void** args) {
    cudaLaunchConfig_t cfg = {};
    cfg.gridDim = grid;
    cfg.blockDim = block;
    cfg.dynamicSmemBytes = smem;
    cudaLaunchAttribute attr[1];
    attr[0].id = cudaLaunchAttributeProgrammaticStreamSerialization;
    attr[0].val.programmaticStreamSerializationAllowed = 1;
    cfg.attrs = attr;
    cfg.numAttrs = 1;
    cfg.stream = 0;
    cudaLaunchKernelExC(&cfg, func, args);
}

extern "C" void kernel_launch(void* const* d_in, const int* in_sizes, int n_in,
                              void* d_out, int out_size) {
    (void)in_sizes; (void)n_in; (void)out_size;
    const float* x    = (const float*)d_in[0];
    const float* Wih0 = (const float*)d_in[1];
    const float* Whh0 = (const float*)d_in[2];
    const float* bih0 = (const float*)d_in[3];
    const float* bhh0 = (const float*)d_in[4];
    const float* Wih1 = (const float*)d_in[5];
    const float* Whh1 = (const float*)d_in[6];
    const float* bih1 = (const float*)d_in[7];
    const float* bhh1 = (const float*)d_in[8];
    const float* Wout = (const float*)d_in[9];
    const float* bout = (const float*)d_in[10];
    float* dout = (float*)d_out;

    cudaFuncSetAttribute(k_rec,        cudaFuncAttributeMaxDynamicSharedMemorySize, SMEMB);
    cudaFuncSetAttribute(k_xg0_all,    cudaFuncAttributeMaxDynamicSharedMemorySize, SMEMB);
    cudaFuncSetAttribute(k_xg1<true>,  cudaFuncAttributeMaxDynamicSharedMemorySize, SMEMB);
    cudaFuncSetAttribute(k_xg1<false>, cudaFuncAttributeMaxDynamicSharedMemorySize, SMEMB);
    cudaFuncSetAttribute(k_xg0_new,    cudaFuncAttributeMaxDynamicSharedMemorySize, SMEMB);
    cudaFuncSetAttribute(k_out,        cudaFuncAttributeMaxDynamicSharedMemorySize, SMEMB);

    k_prep<<<(GG * HH + 255) / 256, 256>>>(Wih0, Whh0, bih0, bhh0,
                                           Wih1, Whh1, bih1, bhh1, Wout);
    k_init<<<(BATCH * TT * KPAD + 255) / 256, 256>>>(x);
    k_xg0_all<<<dim3(16, BATCH * TT / 64), NTH, SMEMB>>>();
    k_gate0_init<<<(BATCH * HH + 255) / 256, 256>>>(0);   // d = 0 only

    for (int d = 0; d < DS; d++) {
        {
            int par0 = 0;
            void* args[] = { &par0 };
            launch_pdl((const void*)&k_xg1<true>, dim3(16, 16), dim3(NTH), SMEMB, args);
        }
        for (int t = 1; t < TT; t++) {
            int par = t & 1, slot = (d + t) % TT;
            {
                void* args[] = { &par, &slot };
                launch_pdl((const void*)&k_rec, dim3(16, 16, 2), dim3(NTH), SMEMB, args);
            }
            {
                void* args[] = { &par };
                launch_pdl((const void*)&k_xg1<false>, dim3(16, 16), dim3(NTH), SMEMB, args);
            }
        }
        {
            int nextslot = (d + 1 < DS) ? (d + 1) % TT : -1;
            void* args[] = { &dout, &d, &bout, &nextslot };
            launch_pdl((const void*)&k_out, dim3(16, 16, 2), dim3(NTH), SMEMB, args);
        }
        if (d + 1 < DS) {
            int slot = d % TT;
            void* args[] = { &slot };
            launch_pdl((const void*)&k_xg0_new, dim3(16, 16), dim3(NTH), SMEMB, args);
        }
    }
}

// round 11
// speedup vs baseline: 1.4993x; 1.4993x over previous
#include <cuda_runtime.h>
#include <cuda_fp16.h>
#include <cstdint>

#define BATCH 1024
#define TT 13
#define YY 188
#define HH 512
#define GG 1536
#define DS 13
#define KPAD 192
#define NTH 128
#define SEPIL 100

// ---------------- scratch ----------------
__device__ float  g_xg0[(size_t)TT * BATCH * GG];   // ring: xg0 + b_ih0 (permuted cols)
__device__ float  g_gh1[(size_t)BATCH * GG];
__device__ float  g_h0[2][(size_t)BATCH * HH];
__device__ __half g_h0f[2][(size_t)BATCH * HH];
__device__ float  g_h1[2][(size_t)BATCH * HH];
__device__ __half g_h1f[2][(size_t)BATCH * HH];
__device__ float  g_xlast[(size_t)BATCH * YY];
__device__ __half g_xlastf[(size_t)BATCH * KPAD];
__device__ __half g_xpf[(size_t)BATCH * TT * KPAD];
__device__ __half g_Whh0h[(size_t)GG * HH];
__device__ __half g_Wih1h[(size_t)GG * HH];
__device__ __half g_Whh1h[(size_t)GG * HH];
__device__ __half g_Wih0h[(size_t)GG * KPAD];
__device__ __half g_Wouth[(size_t)KPAD * HH];
__device__ float g_bih0p[GG], g_bhh0p[GG], g_bih1p[GG], g_bhh1p[GG];

// ---------------- helpers ----------------
__device__ __forceinline__ void cp16(uint32_t d, const void* s) {
    asm volatile("cp.async.cg.shared.global [%0], [%1], 16;\n" :: "r"(d), "l"(s));
}
__device__ __forceinline__ void cpc()  { asm volatile("cp.async.commit_group;\n"); }
__device__ __forceinline__ void cpw1() { asm volatile("cp.async.wait_group 1;\n"); }
__device__ __forceinline__ void gdwait() {
    asm volatile("griddepcontrol.wait;" ::: "memory");
}
__device__ __forceinline__ void gdlaunch() {
    asm volatile("griddepcontrol.launch_dependents;" ::: "memory");
}
__device__ __forceinline__ float sigm(float x)   { return 1.f / (1.f + __expf(-x)); }
__device__ __forceinline__ float tanhf_(float x) { return 2.f * sigm(2.f * x) - 1.f; }

__device__ __forceinline__ void ldm4(uint32_t* r, uint32_t a) {
    asm volatile("ldmatrix.sync.aligned.m8n8.x4.shared.b16 {%0,%1,%2,%3}, [%4];"
        : "=r"(r[0]), "=r"(r[1]), "=r"(r[2]), "=r"(r[3]) : "r"(a));
}
__device__ __forceinline__ uint32_t relu2(uint32_t v) {
    uint32_t r; asm("max.f16x2 %0, %1, %2;" : "=r"(r) : "r"(v), "r"(0u)); return r;
}
__device__ __forceinline__ void mma16(float* d, const uint32_t* a, uint32_t b0, uint32_t b1) {
    asm volatile("mma.sync.aligned.m16n8k16.row.col.f32.f16.f16.f32 "
        "{%0,%1,%2,%3},{%4,%5,%6,%7},{%8,%9},{%0,%1,%2,%3};"
        : "+f"(d[0]), "+f"(d[1]), "+f"(d[2]), "+f"(d[3])
        : "r"(a[0]), "r"(a[1]), "r"(a[2]), "r"(a[3]), "r"(b0), "r"(b1));
}

// modes
#define M_GATE0 0
#define M_GATE1 1
#define M_STORE 2
#define M_XGALL 4
#define M_OUT   5

// ---- GEMM core: BM=64, BN=96, 4 warps (2x2), BK=64 halves, 3-stage, occ 3 ----
#define ASTR  8192      // 64*128 bytes per A stage
#define BSTRb 12288     // 96*128 bytes per B stage
#define SMEMB (3 * (ASTR + BSTRb))   // 61440

template<int MODE, int NK, bool ZG, bool RELU_A>
__device__ __forceinline__ void gcore(
    int m0, int n0,
    const __half* __restrict__ A, int lda,
    const __half* __restrict__ Bw, int ldb,
    const float* __restrict__ biasg,
    const float* __restrict__ gh, const float* __restrict__ bhh,
    const float* __restrict__ hsrc, float* __restrict__ hdst, __half* __restrict__ hdstf,
    float* __restrict__ C, float* __restrict__ dout, int dstep)
{
    extern __shared__ float sm[];
    const uint32_t sAb = (uint32_t)__cvta_generic_to_shared(sm);
    const uint32_t sBb = sAb + 3 * ASTR;

    const int tid = threadIdx.x, lane = tid & 31, warp = tid >> 5;
    const int warpM = warp >> 1, warpN = warp & 1;     // 2 x 2
    const int lane4 = lane >> 2, lq = lane & 3;

    float acc[2][6][4];
#pragma unroll
    for (int i = 0; i < 2; i++)
#pragma unroll
        for (int j = 0; j < 6; j++)
#pragma unroll
            for (int q = 0; q < 4; q++) acc[i][j][q] = 0.f;

    auto loadA = [&](int st, int k0) {
#pragma unroll
        for (int v = tid; v < 64 * 8; v += NTH) {
            int r = v >> 3, vc = v & 7;
            cp16(sAb + st * ASTR + r * 128 + ((vc ^ (r & 7)) << 4),
                 A + (size_t)(m0 + r) * lda + k0 + vc * 8);
        }
    };
    auto loadB = [&](int st, int k0) {
#pragma unroll
        for (int v = tid; v < 96 * 8; v += NTH) {
            int r = v >> 3, vc = v & 7;
            cp16(sBb + st * BSTRb + r * 128 + ((vc ^ (r & 7)) << 4),
                 Bw + (size_t)(n0 + r) * ldb + k0 + vc * 8);
        }
    };

    // B (weights) for stages 0..2 has NO dependency on the predecessor kernel:
    // issue before griddepcontrol.wait so it overlaps the predecessor's drain.
    loadB(0, 0);
    loadB(1, 64);
    loadB(2, 128);
    gdwait();                       // predecessor results now visible
    loadA(0, 0);  cpc();            // G0 = {B0,B1,B2,A0}
    loadA(1, 64); cpc();            // G1 = {A1}

    const int subrow = lane & 7;
    uint32_t aBase[2]; int r7A[2];
#pragma unroll
    for (int i = 0; i < 2; i++) {
        int row = warpM * 32 + i * 16 + subrow + ((lane >> 3) & 1) * 8;
        aBase[i] = sAb + row * 128; r7A[i] = row & 7;
    }
    uint32_t bBase[3]; int r7B[3];
#pragma unroll
    for (int jj = 0; jj < 3; jj++) {
        int row = warpN * 48 + jj * 16 + subrow + (lane >> 4) * 8;
        bBase[jj] = sBb + row * 128; r7B[jj] = row & 7;
    }
    const int kvA = lane >> 4;
    const int kvB = (lane >> 3) & 1;

    uint32_t aF[2][2][4], bF[2][3][4];
    auto ldfr = [&](int st, int ks, int buf) {
#pragma unroll
        for (int i = 0; i < 2; i++) {
            ldm4(aF[buf][i], aBase[i] + st * ASTR + (((2 * ks + kvA) ^ r7A[i]) << 4));
            if (RELU_A) {
#pragma unroll
                for (int q = 0; q < 4; q++) aF[buf][i][q] = relu2(aF[buf][i][q]);
            }
        }
#pragma unroll
        for (int jj = 0; jj < 3; jj++)
            ldm4(bF[buf][jj], bBase[jj] + st * BSTRb + (((2 * ks + kvB) ^ r7B[jj]) << 4));
    };

    for (int kt = 0; kt < NK; kt++) {
        cpw1();                      // all groups except newest complete -> stage kt ready
        __syncthreads();
        if (kt + 2 < NK) {
            int st = (kt + 2) % 3, k0 = (kt + 2) * 64;
            if (kt + 2 >= 3) loadB(st, k0);   // stages 0..2 B pre-issued
            loadA(st, k0);
        }
        cpc();                       // unconditional: keeps group<->stage invariant

        const int st = kt % 3;
        ldfr(st, 0, 0);
#pragma unroll
        for (int ks = 0; ks < 4; ks++) {
            const int cur = ks & 1;
            if (ks < 3) ldfr(st, ks + 1, cur ^ 1);
#pragma unroll
            for (int j = 0; j < 6; j++)
#pragma unroll
                for (int i = 0; i < 2; i++)
                    mma16(acc[i][j], aF[cur][i],
                          bF[cur][j >> 1][(j & 1) * 2], bF[cur][j >> 1][(j & 1) * 2 + 1]);
        }
    }
    __syncthreads();

    // ---------------- epilogues ----------------
    if (MODE == M_STORE || MODE == M_XGALL) {
#pragma unroll
        for (int i = 0; i < 2; i++) {
            int rr = m0 + warpM * 32 + i * 16 + lane4;
#pragma unroll
            for (int j = 0; j < 6; j++) {
                int cc = n0 + warpN * 48 + j * 8 + lq * 2;
#pragma unroll
                for (int q = 0; q < 4; q++) {
                    int r2 = rr + (q >> 1) * 8, c2 = cc + (q & 1);
                    float v = acc[i][j][q] + biasg[c2];
                    if (MODE == M_STORE) {
                        C[(size_t)r2 * GG + c2] = v;
                    } else {
                        int b = r2 / TT, t = r2 % TT;
                        C[((size_t)t * BATCH + b) * GG + c2] = v;
                    }
                }
            }
        }
    } else if (MODE == M_OUT) {
#pragma unroll
        for (int i = 0; i < 2; i++) {
            int rr = m0 + warpM * 32 + i * 16 + lane4;
#pragma unroll
            for (int j = 0; j < 6; j++) {
                int cc = n0 + warpN * 48 + j * 8 + lq * 2;
#pragma unroll
                for (int q = 0; q < 4; q++) {
                    int r2 = rr + (q >> 1) * 8, c2 = cc + (q & 1);
                    if (c2 < YY) {
                        float v = acc[i][j][q] + biasg[c2] + g_xlast[(size_t)r2 * YY + c2];
                        dout[((size_t)r2 * DS + dstep) * YY + c2] = v;
                        g_xlast[(size_t)r2 * YY + c2] = v;
                        g_xlastf[(size_t)r2 * KPAD + c2] = __float2half_rn(v);
                    }
                }
            }
        }
    } else {  // M_GATE0 / M_GATE1: acc -> smem -> fused gate math
#pragma unroll
        for (int i = 0; i < 2; i++) {
            int rl = warpM * 32 + i * 16 + lane4;
#pragma unroll
            for (int j = 0; j < 6; j++) {
                int cl = warpN * 48 + j * 8 + lq * 2;
                *(float2*)&sm[rl * SEPIL + cl]       = make_float2(acc[i][j][0], acc[i][j][1]);
                *(float2*)&sm[(rl + 8) * SEPIL + cl] = make_float2(acc[i][j][2], acc[i][j][3]);
            }
        }
        __syncthreads();
        const int jbase = n0 / 3;   // 32 * blockIdx.x
        for (int idx = tid; idx < 64 * 32; idx += NTH) {
            int bl = idx >> 5, jj = idx & 31;
            int b = m0 + bl;
            int cg = n0 + 3 * jj;
            float ar = sm[bl * SEPIL + 3 * jj + 0];
            float az = sm[bl * SEPIL + 3 * jj + 1];
            float an = sm[bl * SEPIL + 3 * jj + 2];
            float xr, xz, xn, gr, gz, gn, hp;
            if (MODE == M_GATE0) {
                const float* xg = gh + (size_t)b * GG;
                xr = xg[cg]; xz = xg[cg + 1]; xn = xg[cg + 2];
                gr = ar + bhh[cg]; gz = az + bhh[cg + 1]; gn = an + bhh[cg + 2];
                hp = hsrc[(size_t)b * HH + jbase + jj];
            } else {
                xr = ar + biasg[cg]; xz = az + biasg[cg + 1]; xn = an + biasg[cg + 2];
                if (ZG) {
                    gr = bhh[cg]; gz = bhh[cg + 1]; gn = bhh[cg + 2]; hp = 0.f;
                } else {
                    const float* g = gh + (size_t)b * GG;
                    gr = g[cg]; gz = g[cg + 1]; gn = g[cg + 2];
                    hp = hsrc[(size_t)b * HH + jbase + jj];
                }
            }
            float r = sigm(xr + gr), z = sigm(xz + gz);
            float nn_ = tanhf_(xn + r * gn);
            float hv = (1.f - z) * nn_ + z * hp;
            hdst[(size_t)b * HH + jbase + jj] = hv;
            hdstf[(size_t)b * HH + jbase + jj] = __float2half_rn(hv);
        }
    }
}

// ---------------- kernels ----------------
__global__ void __launch_bounds__(NTH, 3) k_rec(int par, int slot) {
    int m0 = blockIdx.y * 64, n0 = blockIdx.x * 96;
    if (blockIdx.z == 0)
        gcore<M_GATE0, 8, false, false>(m0, n0,
            g_h0f[par ^ 1], HH, g_Whh0h, HH, nullptr,
            g_xg0 + (size_t)slot * BATCH * GG, g_bhh0p,
            g_h0[par ^ 1], g_h0[par], g_h0f[par], nullptr, nullptr, 0);
    else
        gcore<M_STORE, 8, false, false>(m0, n0,
            g_h1f[par ^ 1], HH, g_Whh1h, HH, g_bhh1p,
            nullptr, nullptr, nullptr, nullptr, nullptr, g_gh1, nullptr, 0);
    gdlaunch();
}

template<bool ZG>
__global__ void __launch_bounds__(NTH, 3) k_xg1(int par) {
    gcore<M_GATE1, 8, ZG, false>(blockIdx.y * 64, blockIdx.x * 96,
        g_h0f[par], HH, g_Wih1h, HH, g_bih1p, g_gh1, g_bhh1p,
        g_h1[par ^ 1], g_h1[par], g_h1f[par], nullptr, nullptr, 0);
    gdlaunch();
}

__global__ void __launch_bounds__(NTH, 3) k_xg0_all() {
    gcore<M_XGALL, 3, false, false>(blockIdx.y * 64, blockIdx.x * 96,
        g_xpf, KPAD, g_Wih0h, KPAD, g_bih0p,
        nullptr, nullptr, nullptr, nullptr, nullptr, g_xg0, nullptr, 0);
}

__global__ void __launch_bounds__(NTH, 3) k_xg0_new(int slot) {
    gcore<M_STORE, 3, false, false>(blockIdx.y * 64, blockIdx.x * 96,
        g_xlastf, KPAD, g_Wih0h, KPAD, g_bih0p,
        nullptr, nullptr, nullptr, nullptr, nullptr,
        g_xg0 + (size_t)slot * BATCH * GG, nullptr, 0);
    gdlaunch();
}

// grid (16,16,2):
//   z=0, x<2 : output GEMM (+residual+feedback)   [32 CTAs]
//   z=1      : gate0 init for NEXT decode's ring slot [256 CTAs]
__global__ void __launch_bounds__(NTH, 3) k_out(float* __restrict__ dout, int dstep,
                                                const float* __restrict__ bout,
                                                int nextslot) {
    if (blockIdx.z == 1) {
        if (nextslot >= 0) {
            gdwait();
            const float* ring = g_xg0 + (size_t)nextslot * BATCH * GG;
            int base = (blockIdx.y * gridDim.x + blockIdx.x) * NTH + threadIdx.x;
            int stride = gridDim.x * gridDim.y * NTH;
            for (int idx = base; idx < BATCH * HH; idx += stride) {
                int b = idx >> 9, j = idx & 511;
                const float* xg = ring + (size_t)b * GG;
                int c = 3 * j;
                float r = sigm(xg[c] + g_bhh0p[c]);
                float z = sigm(xg[c + 1] + g_bhh0p[c + 1]);
                float n = tanhf_(xg[c + 2] + r * g_bhh0p[c + 2]);
                float hv = (1.f - z) * n;
                g_h0[0][idx] = hv;
                g_h0f[0][idx] = __float2half_rn(hv);
            }
        }
        gdlaunch();
        return;
    }
    if (blockIdx.x < 2) {
        gcore<M_OUT, 8, false, true>(blockIdx.y * 64, blockIdx.x * 96,
            g_h1f[0], HH, g_Wouth, HH, bout, nullptr, nullptr,
            nullptr, nullptr, nullptr, nullptr, dout, dstep);
    }
    gdlaunch();
}

__global__ void k_gate0_init(int slot) {
    int idx = blockIdx.x * blockDim.x + threadIdx.x;
    if (idx >= BATCH * HH) return;
    int b = idx >> 9, j = idx & 511;
    const float* xg = g_xg0 + (size_t)slot * BATCH * GG + (size_t)b * GG;
    int c = 3 * j;
    float r = sigm(xg[c] + g_bhh0p[c]);
    float z = sigm(xg[c + 1] + g_bhh0p[c + 1]);
    float n = tanhf_(xg[c + 2] + r * g_bhh0p[c + 2]);
    float hv = (1.f - z) * n;
    g_h0[0][idx] = hv;
    g_h0f[0][idx] = __float2half_rn(hv);
}

__global__ void k_init(const float* __restrict__ x) {
    int idx = blockIdx.x * blockDim.x + threadIdx.x;
    if (idx < BATCH * TT * KPAD) {
        int row = idx / KPAD, k = idx % KPAD;
        g_xpf[idx] = (k < YY) ? __float2half_rn(x[(size_t)row * YY + k]) : __float2half_rn(0.f);
    }
    if (idx < BATCH * KPAD) {
        int b = idx / KPAD, k = idx % KPAD;
        if (k < YY) {
            float v = x[((size_t)b * TT + (TT - 1)) * YY + k];
            g_xlast[(size_t)b * YY + k] = v;
            g_xlastf[idx] = __float2half_rn(v);
        } else {
            g_xlastf[idx] = __float2half_rn(0.f);
        }
    }
}

__global__ void k_prep(const float* __restrict__ Wih0, const float* __restrict__ Whh0,
                       const float* __restrict__ bih0, const float* __restrict__ bhh0,
                       const float* __restrict__ Wih1, const float* __restrict__ Whh1,
                       const float* __restrict__ bih1, const float* __restrict__ bhh1,
                       const float* __restrict__ Wout) {
    int i = blockIdx.x * blockDim.x + threadIdx.x;
    if (i < GG * HH) {
        int c = i / HH, k = i % HH;
        int pr = (c % 3) * HH + c / 3;
        g_Whh0h[i] = __float2half_rn(Whh0[(size_t)pr * HH + k]);
        g_Wih1h[i] = __float2half_rn(Wih1[(size_t)pr * HH + k]);
        g_Whh1h[i] = __float2half_rn(Whh1[(size_t)pr * HH + k]);
    }
    if (i < GG * KPAD) {
        int c = i / KPAD, k = i % KPAD;
        int pr = (c % 3) * HH + c / 3;
        g_Wih0h[i] = (k < YY) ? __float2half_rn(Wih0[(size_t)pr * YY + k]) : __float2half_rn(0.f);
    }
    if (i < KPAD * HH) {
        int r = i / HH, k = i % HH;
        g_Wouth[i] = (r < YY) ? __float2half_rn(Wout[(size_t)r * HH + k]) : __float2half_rn(0.f);
    }
    if (i < GG) {
        int pr = (i % 3) * HH + i / 3;
        g_bih0p[i] = bih0[pr];
        g_bhh0p[i] = bhh0[pr];
        g_bih1p[i] = bih1[pr];
        g_bhh1p[i] = bhh1[pr];
    }
}

// ---------------- host ----------------
static void launch_pdl(const void* func, dim3 grid, dim3 block, size_t smem, void** args) {
    cudaLaunchConfig_t cfg = {};
    cfg.gridDim = grid;
    cfg.blockDim = block;
    cfg.dynamicSmemBytes = smem;
    cudaLaunchAttribute attr[1];
    attr[0].id = cudaLaunchAttributeProgrammaticStreamSerialization;
    attr[0].val.programmaticStreamSerializationAllowed = 1;
    cfg.attrs = attr;
    cfg.numAttrs = 1;
    cfg.stream = 0;
    cudaLaunchKernelExC(&cfg, func, args);
}

extern "C" void kernel_launch(void* const* d_in, const int* in_sizes, int n_in,
                              void* d_out, int out_size) {
    (void)in_sizes; (void)n_in; (void)out_size;
    const float* x    = (const float*)d_in[0];
    const float* Wih0 = (const float*)d_in[1];
    const float* Whh0 = (const float*)d_in[2];
    const float* bih0 = (const float*)d_in[3];
    const float* bhh0 = (const float*)d_in[4];
    const float* Wih1 = (const float*)d_in[5];
    const float* Whh1 = (const float*)d_in[6];
    const float* bih1 = (const float*)d_in[7];
    const float* bhh1 = (const float*)d_in[8];
    const float* Wout = (const float*)d_in[9];
    const float* bout = (const float*)d_in[10];
    float* dout = (float*)d_out;

    cudaFuncSetAttribute(k_rec,        cudaFuncAttributeMaxDynamicSharedMemorySize, SMEMB);
    cudaFuncSetAttribute(k_xg0_all,    cudaFuncAttributeMaxDynamicSharedMemorySize, SMEMB);
    cudaFuncSetAttribute(k_xg1<true>,  cudaFuncAttributeMaxDynamicSharedMemorySize, SMEMB);
    cudaFuncSetAttribute(k_xg1<false>, cudaFuncAttributeMaxDynamicSharedMemorySize, SMEMB);
    cudaFuncSetAttribute(k_xg0_new,    cudaFuncAttributeMaxDynamicSharedMemorySize, SMEMB);
    cudaFuncSetAttribute(k_out,        cudaFuncAttributeMaxDynamicSharedMemorySize, SMEMB);

    k_prep<<<(GG * HH + 255) / 256, 256>>>(Wih0, Whh0, bih0, bhh0,
                                           Wih1, Whh1, bih1, bhh1, Wout);
    k_init<<<(BATCH * TT * KPAD + 255) / 256, 256>>>(x);
    k_xg0_all<<<dim3(16, BATCH * TT / 64), NTH, SMEMB>>>();
    k_gate0_init<<<(BATCH * HH + 255) / 256, 256>>>(0);   // d = 0 only

    for (int d = 0; d < DS; d++) {
        {
            int par0 = 0;
            void* args[] = { &par0 };
            launch_pdl((const void*)&k_xg1<true>, dim3(16, 16), dim3(NTH), SMEMB, args);
        }
        for (int t = 1; t < TT; t++) {
            int par = t & 1, slot = (d + t) % TT;
            {
                void* args[] = { &par, &slot };
                launch_pdl((const void*)&k_rec, dim3(16, 16, 2), dim3(NTH), SMEMB, args);
            }
            {
                void* args[] = { &par };
                launch_pdl((const void*)&k_xg1<false>, dim3(16, 16), dim3(NTH), SMEMB, args);
            }
        }
        {
            int nextslot = (d + 1 < DS) ? (d + 1) % TT : -1;
            void* args[] = { &dout, &d, &bout, &nextslot };
            launch_pdl((const void*)&k_out, dim3(16, 16, 2), dim3(NTH), SMEMB, args);
        }
        if (d + 1 < DS) {
            int slot = d % TT;
            void* args[] = { &slot };
            launch_pdl((const void*)&k_xg0_new, dim3(16, 16), dim3(NTH), SMEMB, args);
        }
    }
}

// round 12
// speedup vs baseline: 1.5298x; 1.0203x over previous
#include <cuda_runtime.h>
#include <cuda_fp16.h>
#include <cstdint>

#define BATCH 1024
#define TT 13
#define YY 188
#define HH 512
#define GG 1536
#define DS 13
#define KPAD 192
#define NTH 128
#define SEPIL 100

// ---------------- scratch ----------------
__device__ float  g_xg0[(size_t)TT * BATCH * GG];   // ring: xg0 + b_ih0 (permuted cols)
__device__ float  g_xg1r[2][(size_t)BATCH * GG];    // raw xg1 (+b_ih1), parity by t
__device__ float  g_h0[2][(size_t)BATCH * HH];
__device__ __half g_h0f[2][(size_t)BATCH * HH];
__device__ float  g_h1[2][(size_t)BATCH * HH];
__device__ __half g_h1f[2][(size_t)BATCH * HH];
__device__ float  g_xlast[(size_t)BATCH * YY];
__device__ __half g_xlastf[(size_t)BATCH * KPAD];
__device__ __half g_xpf[(size_t)BATCH * TT * KPAD];
__device__ __half g_Whh0h[(size_t)GG * HH];
__device__ __half g_Wih1h[(size_t)GG * HH];
__device__ __half g_Whh1h[(size_t)GG * HH];
__device__ __half g_Wih0h[(size_t)GG * KPAD];
__device__ __half g_Wouth[(size_t)KPAD * HH];
__device__ float g_bih0p[GG], g_bhh0p[GG], g_bih1p[GG], g_bhh1p[GG];

// ---------------- helpers ----------------
__device__ __forceinline__ void cp16(uint32_t d, const void* s) {
    asm volatile("cp.async.cg.shared.global [%0], [%1], 16;\n" :: "r"(d), "l"(s));
}
__device__ __forceinline__ void cpc()  { asm volatile("cp.async.commit_group;\n"); }
__device__ __forceinline__ void cpw1() { asm volatile("cp.async.wait_group 1;\n"); }
__device__ __forceinline__ void gdwait() {
    asm volatile("griddepcontrol.wait;" ::: "memory");
}
__device__ __forceinline__ void gdlaunch() {
    asm volatile("griddepcontrol.launch_dependents;" ::: "memory");
}
__device__ __forceinline__ float sigm(float x)   { return 1.f / (1.f + __expf(-x)); }
__device__ __forceinline__ float tanhf_(float x) { return 2.f * sigm(2.f * x) - 1.f; }

__device__ __forceinline__ void ldm4(uint32_t* r, uint32_t a) {
    asm volatile("ldmatrix.sync.aligned.m8n8.x4.shared.b16 {%0,%1,%2,%3}, [%4];"
        : "=r"(r[0]), "=r"(r[1]), "=r"(r[2]), "=r"(r[3]) : "r"(a));
}
__device__ __forceinline__ uint32_t relu2(uint32_t v) {
    uint32_t r; asm("max.f16x2 %0, %1, %2;" : "=r"(r) : "r"(v), "r"(0u)); return r;
}
__device__ __forceinline__ void mma16(float* d, const uint32_t* a, uint32_t b0, uint32_t b1) {
    asm volatile("mma.sync.aligned.m16n8k16.row.col.f32.f16.f16.f32 "
        "{%0,%1,%2,%3},{%4,%5,%6,%7},{%8,%9},{%0,%1,%2,%3};"
        : "+f"(d[0]), "+f"(d[1]), "+f"(d[2]), "+f"(d[3])
        : "r"(a[0]), "r"(a[1]), "r"(a[2]), "r"(a[3]), "r"(b0), "r"(b1));
}

// modes
#define M_GATE0 0
#define M_GATE1 1
#define M_STORE 2
#define M_XGALL 4
#define M_OUT   5

// ---- GEMM core: BM=64, BN=96, 4 warps (2x2), BK=64 halves, 3-stage, occ 3 ----
#define ASTR  8192      // 64*128 bytes per A stage
#define BSTRb 12288     // 96*128 bytes per B stage
#define SMEMB (3 * (ASTR + BSTRb))   // 61440

template<int MODE, int NK, bool ZG, bool RELU_A>
__device__ __forceinline__ void gcore(
    int m0, int n0,
    const __half* __restrict__ A, int lda,
    const __half* __restrict__ Bw, int ldb,
    const float* __restrict__ biasg,
    const float* __restrict__ gh, const float* __restrict__ bhh,
    const float* __restrict__ hsrc, float* __restrict__ hdst, __half* __restrict__ hdstf,
    float* __restrict__ C, float* __restrict__ dout, int dstep)
{
    extern __shared__ float sm[];
    const uint32_t sAb = (uint32_t)__cvta_generic_to_shared(sm);
    const uint32_t sBb = sAb + 3 * ASTR;

    const int tid = threadIdx.x, lane = tid & 31, warp = tid >> 5;
    const int warpM = warp >> 1, warpN = warp & 1;     // 2 x 2
    const int lane4 = lane >> 2, lq = lane & 3;

    float acc[2][6][4];
#pragma unroll
    for (int i = 0; i < 2; i++)
#pragma unroll
        for (int j = 0; j < 6; j++)
#pragma unroll
            for (int q = 0; q < 4; q++) acc[i][j][q] = 0.f;

    auto loadA = [&](int st, int k0) {
#pragma unroll
        for (int v = tid; v < 64 * 8; v += NTH) {
            int r = v >> 3, vc = v & 7;
            cp16(sAb + st * ASTR + r * 128 + ((vc ^ (r & 7)) << 4),
                 A + (size_t)(m0 + r) * lda + k0 + vc * 8);
        }
    };
    auto loadB = [&](int st, int k0) {
#pragma unroll
        for (int v = tid; v < 96 * 8; v += NTH) {
            int r = v >> 3, vc = v & 7;
            cp16(sBb + st * BSTRb + r * 128 + ((vc ^ (r & 7)) << 4),
                 Bw + (size_t)(n0 + r) * ldb + k0 + vc * 8);
        }
    };

    // B (weights) for stages 0..2 has NO dependency on the predecessor kernel:
    // issue before griddepcontrol.wait so it overlaps the predecessor's drain.
    loadB(0, 0);
    loadB(1, 64);
    loadB(2, 128);
    gdwait();                       // predecessor results now visible
    loadA(0, 0);  cpc();            // G0 = {B0,B1,B2,A0}
    loadA(1, 64); cpc();            // G1 = {A1}

    const int subrow = lane & 7;
    uint32_t aBase[2]; int r7A[2];
#pragma unroll
    for (int i = 0; i < 2; i++) {
        int row = warpM * 32 + i * 16 + subrow + ((lane >> 3) & 1) * 8;
        aBase[i] = sAb + row * 128; r7A[i] = row & 7;
    }
    uint32_t bBase[3]; int r7B[3];
#pragma unroll
    for (int jj = 0; jj < 3; jj++) {
        int row = warpN * 48 + jj * 16 + subrow + (lane >> 4) * 8;
        bBase[jj] = sBb + row * 128; r7B[jj] = row & 7;
    }
    const int kvA = lane >> 4;
    const int kvB = (lane >> 3) & 1;

    uint32_t aF[2][2][4], bF[2][3][4];
    auto ldfr = [&](int st, int ks, int buf) {
#pragma unroll
        for (int i = 0; i < 2; i++) {
            ldm4(aF[buf][i], aBase[i] + st * ASTR + (((2 * ks + kvA) ^ r7A[i]) << 4));
            if (RELU_A) {
#pragma unroll
                for (int q = 0; q < 4; q++) aF[buf][i][q] = relu2(aF[buf][i][q]);
            }
        }
#pragma unroll
        for (int jj = 0; jj < 3; jj++)
            ldm4(bF[buf][jj], bBase[jj] + st * BSTRb + (((2 * ks + kvB) ^ r7B[jj]) << 4));
    };

    for (int kt = 0; kt < NK; kt++) {
        cpw1();                      // all groups except newest complete -> stage kt ready
        __syncthreads();
        if (kt + 2 < NK) {
            int st = (kt + 2) % 3, k0 = (kt + 2) * 64;
            if (kt + 2 >= 3) loadB(st, k0);   // stages 0..2 B pre-issued
            loadA(st, k0);
        }
        cpc();                       // unconditional: keeps group<->stage invariant

        const int st = kt % 3;
        ldfr(st, 0, 0);
#pragma unroll
        for (int ks = 0; ks < 4; ks++) {
            const int cur = ks & 1;
            if (ks < 3) ldfr(st, ks + 1, cur ^ 1);
#pragma unroll
            for (int j = 0; j < 6; j++)
#pragma unroll
                for (int i = 0; i < 2; i++)
                    mma16(acc[i][j], aF[cur][i],
                          bF[cur][j >> 1][(j & 1) * 2], bF[cur][j >> 1][(j & 1) * 2 + 1]);
        }
    }
    __syncthreads();

    // ---------------- epilogues ----------------
    if (MODE == M_STORE || MODE == M_XGALL) {
#pragma unroll
        for (int i = 0; i < 2; i++) {
            int rr = m0 + warpM * 32 + i * 16 + lane4;
#pragma unroll
            for (int j = 0; j < 6; j++) {
                int cc = n0 + warpN * 48 + j * 8 + lq * 2;
#pragma unroll
                for (int q = 0; q < 4; q++) {
                    int r2 = rr + (q >> 1) * 8, c2 = cc + (q & 1);
                    float v = acc[i][j][q] + biasg[c2];
                    if (MODE == M_STORE) {
                        C[(size_t)r2 * GG + c2] = v;
                    } else {
                        int b = r2 / TT, t = r2 % TT;
                        C[((size_t)t * BATCH + b) * GG + c2] = v;
                    }
                }
            }
        }
    } else if (MODE == M_OUT) {
#pragma unroll
        for (int i = 0; i < 2; i++) {
            int rr = m0 + warpM * 32 + i * 16 + lane4;
#pragma unroll
            for (int j = 0; j < 6; j++) {
                int cc = n0 + warpN * 48 + j * 8 + lq * 2;
#pragma unroll
                for (int q = 0; q < 4; q++) {
                    int r2 = rr + (q >> 1) * 8, c2 = cc + (q & 1);
                    if (c2 < YY) {
                        float v = acc[i][j][q] + biasg[c2] + g_xlast[(size_t)r2 * YY + c2];
                        dout[((size_t)r2 * DS + dstep) * YY + c2] = v;
                        g_xlast[(size_t)r2 * YY + c2] = v;
                        g_xlastf[(size_t)r2 * KPAD + c2] = __float2half_rn(v);
                    }
                }
            }
        }
    } else {  // M_GATE0 / M_GATE1: acc -> smem -> fused gate math
#pragma unroll
        for (int i = 0; i < 2; i++) {
            int rl = warpM * 32 + i * 16 + lane4;
#pragma unroll
            for (int j = 0; j < 6; j++) {
                int cl = warpN * 48 + j * 8 + lq * 2;
                *(float2*)&sm[rl * SEPIL + cl]       = make_float2(acc[i][j][0], acc[i][j][1]);
                *(float2*)&sm[(rl + 8) * SEPIL + cl] = make_float2(acc[i][j][2], acc[i][j][3]);
            }
        }
        __syncthreads();
        const int jbase = n0 / 3;   // 32 * blockIdx.x
        for (int idx = tid; idx < 64 * 32; idx += NTH) {
            int bl = idx >> 5, jj = idx & 31;
            int b = m0 + bl;
            int cg = n0 + 3 * jj;
            float ar = sm[bl * SEPIL + 3 * jj + 0];
            float az = sm[bl * SEPIL + 3 * jj + 1];
            float an = sm[bl * SEPIL + 3 * jj + 2];
            float xr, xz, xn, gr, gz, gn, hp;
            if (MODE == M_GATE0) {
                const float* xg = gh + (size_t)b * GG;   // x-side pre-stored WITH bias
                xr = xg[cg]; xz = xg[cg + 1]; xn = xg[cg + 2];
                gr = ar + bhh[cg]; gz = az + bhh[cg + 1]; gn = an + bhh[cg + 2];
                hp = hsrc[(size_t)b * HH + jbase + jj];
            } else {
                xr = ar + biasg[cg]; xz = az + biasg[cg + 1]; xn = an + biasg[cg + 2];
                if (ZG) {
                    gr = bhh[cg]; gz = bhh[cg + 1]; gn = bhh[cg + 2]; hp = 0.f;
                } else {
                    const float* g = gh + (size_t)b * GG;
                    gr = g[cg]; gz = g[cg + 1]; gn = g[cg + 2];
                    hp = hsrc[(size_t)b * HH + jbase + jj];
                }
            }
            float r = sigm(xr + gr), z = sigm(xz + gz);
            float nn_ = tanhf_(xn + r * gn);
            float hv = (1.f - z) * nn_ + z * hp;
            hdst[(size_t)b * HH + jbase + jj] = hv;
            hdstf[(size_t)b * HH + jbase + jj] = __float2half_rn(hv);
        }
    }
}

// ---------------- wavefront phase kernel ----------------
// phase p of decode d; grid (16,16,3):
//   z=0: G0(t=p)     : gh0 GEMM + fused gate0 -> h0(p)                (p<=12)
//   z=1: X1(t=p-1)   : xg1 GEMM; t==0 -> fused ZG gate1 -> h1(0)
//                      t>=1 -> raw store (+b_ih1) into g_xg1r[t&1]    (p-1<=12)
//   z=2: G1(t=p-2)   : gh1 GEMM + fused full gate1 (x-side from
//                      g_xg1r[t&1]) -> h1(p-2)                        (1<=p-2<=12)
__global__ void __launch_bounds__(NTH, 3) k_phase(int d, int p) {
    int m0 = blockIdx.y * 64, n0 = blockIdx.x * 96;
    if (blockIdx.z == 0) {
        int t = p;
        if (t <= 12) {
            int slot = (d + t) % TT;
            gcore<M_GATE0, 8, false, false>(m0, n0,
                g_h0f[(t - 1) & 1], HH, g_Whh0h, HH, nullptr,
                g_xg0 + (size_t)slot * BATCH * GG, g_bhh0p,
                g_h0[(t - 1) & 1], g_h0[t & 1], g_h0f[t & 1],
                nullptr, nullptr, 0);
        }
    } else if (blockIdx.z == 1) {
        int t = p - 1;
        if (t <= 12) {
            if (t == 0)
                gcore<M_GATE1, 8, true, false>(m0, n0,
                    g_h0f[0], HH, g_Wih1h, HH, g_bih1p,
                    nullptr, g_bhh1p,
                    nullptr, g_h1[0], g_h1f[0], nullptr, nullptr, 0);
            else
                gcore<M_STORE, 8, false, false>(m0, n0,
                    g_h0f[t & 1], HH, g_Wih1h, HH, g_bih1p,
                    nullptr, nullptr, nullptr, nullptr, nullptr,
                    g_xg1r[t & 1], nullptr, 0);
        }
    } else {
        int t = p - 2;
        if (t >= 1 && t <= 12) {
            gcore<M_GATE0, 8, false, false>(m0, n0,
                g_h1f[(t - 1) & 1], HH, g_Whh1h, HH, nullptr,
                g_xg1r[t & 1], g_bhh1p,
                g_h1[(t - 1) & 1], g_h1[t & 1], g_h1f[t & 1],
                nullptr, nullptr, 0);
        }
    }
    gdlaunch();
}

__global__ void __launch_bounds__(NTH, 3) k_xg0_all() {
    gcore<M_XGALL, 3, false, false>(blockIdx.y * 64, blockIdx.x * 96,
        g_xpf, KPAD, g_Wih0h, KPAD, g_bih0p,
        nullptr, nullptr, nullptr, nullptr, nullptr, g_xg0, nullptr, 0);
}

__global__ void __launch_bounds__(NTH, 3) k_xg0_new(int slot) {
    gcore<M_STORE, 3, false, false>(blockIdx.y * 64, blockIdx.x * 96,
        g_xlastf, KPAD, g_Wih0h, KPAD, g_bih0p,
        nullptr, nullptr, nullptr, nullptr, nullptr,
        g_xg0 + (size_t)slot * BATCH * GG, nullptr, 0);
    gdlaunch();
}

// grid (16,16,2):
//   z=0, x<2 : output GEMM (+residual+feedback)   [32 CTAs]
//   z=1      : gate0 init for NEXT decode's ring slot [256 CTAs]
__global__ void __launch_bounds__(NTH, 3) k_out(float* __restrict__ dout, int dstep,
                                                const float* __restrict__ bout,
                                                int nextslot) {
    if (blockIdx.z == 1) {
        if (nextslot >= 0) {
            gdwait();
            const float* ring = g_xg0 + (size_t)nextslot * BATCH * GG;
            int base = (blockIdx.y * gridDim.x + blockIdx.x) * NTH + threadIdx.x;
            int stride = gridDim.x * gridDim.y * NTH;
            for (int idx = base; idx < BATCH * HH; idx += stride) {
                int b = idx >> 9, j = idx & 511;
                const float* xg = ring + (size_t)b * GG;
                int c = 3 * j;
                float r = sigm(xg[c] + g_bhh0p[c]);
                float z = sigm(xg[c + 1] + g_bhh0p[c + 1]);
                float n = tanhf_(xg[c + 2] + r * g_bhh0p[c + 2]);
                float hv = (1.f - z) * n;
                g_h0[0][idx] = hv;
                g_h0f[0][idx] = __float2half_rn(hv);
            }
        }
        gdlaunch();
        return;
    }
    if (blockIdx.x < 2) {
        gcore<M_OUT, 8, false, true>(blockIdx.y * 64, blockIdx.x * 96,
            g_h1f[0], HH, g_Wouth, HH, bout, nullptr, nullptr,
            nullptr, nullptr, nullptr, nullptr, dout, dstep);
    }
    gdlaunch();
}

__global__ void k_gate0_init(int slot) {
    int idx = blockIdx.x * blockDim.x + threadIdx.x;
    if (idx >= BATCH * HH) return;
    int b = idx >> 9, j = idx & 511;
    const float* xg = g_xg0 + (size_t)slot * BATCH * GG + (size_t)b * GG;
    int c = 3 * j;
    float r = sigm(xg[c] + g_bhh0p[c]);
    float z = sigm(xg[c + 1] + g_bhh0p[c + 1]);
    float n = tanhf_(xg[c + 2] + r * g_bhh0p[c + 2]);
    float hv = (1.f - z) * n;
    g_h0[0][idx] = hv;
    g_h0f[0][idx] = __float2half_rn(hv);
}

__global__ void k_init(const float* __restrict__ x) {
    int idx = blockIdx.x * blockDim.x + threadIdx.x;
    if (idx < BATCH * TT * KPAD) {
        int row = idx / KPAD, k = idx % KPAD;
        g_xpf[idx] = (k < YY) ? __float2half_rn(x[(size_t)row * YY + k]) : __float2half_rn(0.f);
    }
    if (idx < BATCH * KPAD) {
        int b = idx / KPAD, k = idx % KPAD;
        if (k < YY) {
            float v = x[((size_t)b * TT + (TT - 1)) * YY + k];
            g_xlast[(size_t)b * YY + k] = v;
            g_xlastf[idx] = __float2half_rn(v);
        } else {
            g_xlastf[idx] = __float2half_rn(0.f);
        }
    }
}

__global__ void k_prep(const float* __restrict__ Wih0, const float* __restrict__ Whh0,
                       const float* __restrict__ bih0, const float* __restrict__ bhh0,
                       const float* __restrict__ Wih1, const float* __restrict__ Whh1,
                       const float* __restrict__ bih1, const float* __restrict__ bhh1,
                       const float* __restrict__ Wout) {
    int i = blockIdx.x * blockDim.x + threadIdx.x;
    if (i < GG * HH) {
        int c = i / HH, k = i % HH;
        int pr = (c % 3) * HH + c / 3;
        g_Whh0h[i] = __float2half_rn(Whh0[(size_t)pr * HH + k]);
        g_Wih1h[i] = __float2half_rn(Wih1[(size_t)pr * HH + k]);
        g_Whh1h[i] = __float2half_rn(Whh1[(size_t)pr * HH + k]);
    }
    if (i < GG * KPAD) {
        int c = i / KPAD, k = i % KPAD;
        int pr = (c % 3) * HH + c / 3;
        g_Wih0h[i] = (k < YY) ? __float2half_rn(Wih0[(size_t)pr * YY + k]) : __float2half_rn(0.f);
    }
    if (i < KPAD * HH) {
        int r = i / HH, k = i % HH;
        g_Wouth[i] = (r < YY) ? __float2half_rn(Wout[(size_t)r * HH + k]) : __float2half_rn(0.f);
    }
    if (i < GG) {
        int pr = (i % 3) * HH + i / 3;
        g_bih0p[i] = bih0[pr];
        g_bhh0p[i] = bhh0[pr];
        g_bih1p[i] = bih1[pr];
        g_bhh1p[i] = bhh1[pr];
    }
}

// ---------------- host ----------------
static void launch_pdl(const void* func, dim3 grid, dim3 block, size_t smem, void** args) {
    cudaLaunchConfig_t cfg = {};
    cfg.gridDim = grid;
    cfg.blockDim = block;
    cfg.dynamicSmemBytes = smem;
    cudaLaunchAttribute attr[1];
    attr[0].id = cudaLaunchAttributeProgrammaticStreamSerialization;
    attr[0].val.programmaticStreamSerializationAllowed = 1;
    cfg.attrs = attr;
    cfg.numAttrs = 1;
    cfg.stream = 0;
    cudaLaunchKernelExC(&cfg, func, args);
}

extern "C" void kernel_launch(void* const* d_in, const int* in_sizes, int n_in,
                              void* d_out, int out_size) {
    (void)in_sizes; (void)n_in; (void)out_size;
    const float* x    = (const float*)d_in[0];
    const float* Wih0 = (const float*)d_in[1];
    const float* Whh0 = (const float*)d_in[2];
    const float* bih0 = (const float*)d_in[3];
    const float* bhh0 = (const float*)d_in[4];
    const float* Wih1 = (const float*)d_in[5];
    const float* Whh1 = (const float*)d_in[6];
    const float* bih1 = (const float*)d_in[7];
    const float* bhh1 = (const float*)d_in[8];
    const float* Wout = (const float*)d_in[9];
    const float* bout = (const float*)d_in[10];
    float* dout = (float*)d_out;

    cudaFuncSetAttribute(k_phase,   cudaFuncAttributeMaxDynamicSharedMemorySize, SMEMB);
    cudaFuncSetAttribute(k_xg0_all, cudaFuncAttributeMaxDynamicSharedMemorySize, SMEMB);
    cudaFuncSetAttribute(k_xg0_new, cudaFuncAttributeMaxDynamicSharedMemorySize, SMEMB);
    cudaFuncSetAttribute(k_out,     cudaFuncAttributeMaxDynamicSharedMemorySize, SMEMB);

    k_prep<<<(GG * HH + 255) / 256, 256>>>(Wih0, Whh0, bih0, bhh0,
                                           Wih1, Whh1, bih1, bhh1, Wout);
    k_init<<<(BATCH * TT * KPAD + 255) / 256, 256>>>(x);
    k_xg0_all<<<dim3(16, BATCH * TT / 64), NTH, SMEMB>>>();
    k_gate0_init<<<(BATCH * HH + 255) / 256, 256>>>(0);   // d = 0 only

    for (int d = 0; d < DS; d++) {
        for (int p = 1; p <= 14; p++) {
            void* args[] = { &d, &p };
            launch_pdl((const void*)&k_phase, dim3(16, 16, 3), dim3(NTH), SMEMB, args);
        }
        {
            int nextslot = (d + 1 < DS) ? (d + 1) % TT : -1;
            void* args[] = { &dout, &d, &bout, &nextslot };
            launch_pdl((const void*)&k_out, dim3(16, 16, 2), dim3(NTH), SMEMB, args);
        }
        if (d + 1 < DS) {
            int slot = d % TT;
            void* args[] = { &slot };
            launch_pdl((const void*)&k_xg0_new, dim3(16, 16), dim3(NTH), SMEMB, args);
        }
    }
}